// round 9
// baseline (speedup 1.0000x reference)
#include <cuda_runtime.h>
#include <cstdint>

// Problem constants
#define NN    8192
#define NP1   8193
#define PER   8194ULL                     // diagonal period = NP1 + 1
#define AB    16384ULL                    // A_low base (floats)
#define MM    67125249ULL                 // NP1*NP1
#define AUB   67141633ULL                 // A_up base = AB + MM
#define LR0   134258689ULL                // A_up last row start
#define T_TOT 134266882ULL                // total floats

// Region split (floats):
//   head  [0, 16384)            -> conc_low | conc_up       (head/tail block)
//   fill  [16384, 134258688)    -> grid-stride float4 sweep (zeros + diagonals)
//   tail  [134258688, T_TOT)    -> 1 zero + A_up last row   (head/tail block)
#define VFILL_BEG  4096ULL                // first fill vector (pos/4)
#define VFILL_END  33564672ULL            // one past last fill vector (pos 134258688)
#define TAIL_POS   134258688ULL
#define TAIL_N     8194

#define THREADS      256
#define FILL_BLOCKS  1184
#define STRIDE       ((size_t)FILL_BLOCKS * THREADS)   // 303104 threads
#define RSTEP        7898u                // (4*STRIDE) mod 8194

__global__ void __launch_bounds__(THREADS) relu_relax_onepass(
        const float* __restrict__ lower,
        const float* __restrict__ upper,
        const float* __restrict__ alphas,
        float* __restrict__ out) {
    const int tid = threadIdx.x;

    // ---------------- head + tail block ----------------
    if (blockIdx.x == FILL_BLOCKS) {
        // Head: conc_low | conc_up as float4 (4096 vectors, 16 iters/thread)
        float4* __restrict__ out4 = reinterpret_cast<float4*>(out);
        for (int v = tid; v < 4096; v += THREADS) {
            const int i0 = (v << 2) & (NN - 1);
            const float4 l4 = *reinterpret_cast<const float4*>(lower + i0);
            const float4 u4 = *reinterpret_cast<const float4*>(upper + i0);
            float4 o;
            if (v < 2048) {
                const float4 a4 = *reinterpret_cast<const float4*>(alphas + i0);
                #define CL(lx, ux, ax) \
                    (((ux) > 0.f && (lx) >= 0.f) ? (lx) : \
                     (((ux) > 0.f && (lx) < 0.f) ? fminf(fmaxf((ax),0.f),1.f)*(lx) : 0.f))
                o.x = CL(l4.x, u4.x, a4.x);
                o.y = CL(l4.y, u4.y, a4.y);
                o.z = CL(l4.z, u4.z, a4.z);
                o.w = CL(l4.w, u4.w, a4.w);
                #undef CL
            } else {
                o.x = (u4.x > 0.f) ? u4.x : 0.f;
                o.y = (u4.y > 0.f) ? u4.y : 0.f;
                o.z = (u4.z > 0.f) ? u4.z : 0.f;
                o.w = (u4.w > 0.f) ? u4.w : 0.f;
            }
            out4[v] = o;
        }
        // Tail: float TAIL_POS is interior zero; then A_up last row cols 0..NN.
        for (int t = tid; t < TAIL_N; t += THREADS) {
            float val;
            if (t == 0) {
                val = 0.f;                      // interior element before last row
            } else {
                const int col = t - 1;
                if (col == NN) {
                    val = 1.f;                  // A_up[N][N]
                } else {
                    const float l = lower[col];
                    const float u = upper[col];
                    const bool unstable = (u > 0.f) && (l < 0.f);
                    const float d = u - l;
                    const float lam = u / ((d == 0.f) ? 1.f : d);
                    val = unstable ? (-lam * l) : 0.f;
                }
            }
            out[TAIL_POS + (size_t)t] = val;
        }
        return;
    }

    // ---------------- grid-stride fill of the matrix interior ----------------
    const size_t gtid = (size_t)blockIdx.x * THREADS + tid;
    float4* __restrict__ out4 = reinterpret_cast<float4*>(out);
    const float4 z = make_float4(0.f, 0.f, 0.f, 0.f);

    // r = (4*v - AB) mod 8194 for v = VFILL_BEG + gtid  ==  (4*gtid) mod 8194
    uint32_t r = (uint32_t)((4ULL * gtid) % PER);

    for (size_t v = VFILL_BEG + gtid; v < VFILL_END; v += STRIDE) {
        // Hit iff some lane j in [0,4) has (r+j) mod 8194 in {0 (A_low diag),
        // 1 (A_up diag)}  <=>  r<=1 or r>=8191.
        if (__builtin_expect(r <= 1u || r >= 8191u, 0)) {
            const size_t pos = v << 2;
            float4 o = z;
            float* lanes = reinterpret_cast<float*>(&o);
            #pragma unroll
            for (int j = 0; j < 4; j++) {
                const size_t m = pos + (size_t)j;
                float x = 0.f;
                if (m < AUB) {                       // A_low region (incl corner)
                    const size_t q = m - AB;
                    if (q % PER == 0) {
                        const size_t k = q / PER;
                        if (k == (size_t)NN) {
                            x = 1.f;                 // A_low[N][N]
                        } else {
                            const float l = lower[k];
                            const float u = upper[k];
                            const bool active   = (u > 0.f) && (l >= 0.f);
                            const bool unstable = (u > 0.f) && (l < 0.f);
                            const float a = fminf(fmaxf(alphas[k], 0.f), 1.f);
                            x = active ? 1.f : (unstable ? a : 0.f);
                        }
                    }
                } else {                             // A_up region (k = 0..NN-1 here)
                    const size_t q = m - AUB;
                    if (q % PER == 0) {
                        const size_t k = q / PER;
                        const float l = lower[k];
                        const float u = upper[k];
                        const bool active   = (u > 0.f) && (l >= 0.f);
                        const bool unstable = (u > 0.f) && (l < 0.f);
                        const float d = u - l;
                        const float lam = u / ((d == 0.f) ? 1.f : d);
                        x = active ? 1.f : (unstable ? lam : 0.f);
                    }
                }
                lanes[j] = x;
            }
            out4[v] = o;
        } else {
            out4[v] = z;
        }
        r += RSTEP;
        if (r >= (uint32_t)PER) r -= (uint32_t)PER;
    }
}

extern "C" void kernel_launch(void* const* d_in, const int* in_sizes, int n_in,
                              void* d_out, int out_size) {
    const float* lower  = (const float*)d_in[0];
    const float* upper  = (const float*)d_in[1];
    const float* alphas = (const float*)d_in[2];
    float* out = (float*)d_out;

    relu_relax_onepass<<<FILL_BLOCKS + 1, THREADS>>>(lower, upper, alphas, out);
}